// round 1
// baseline (speedup 1.0000x reference)
#include <cuda_runtime.h>
#include <math.h>

#define Bn 2
#define Nn 512
#define Dn 64
#define EPSf 1e-8f

// ---- output section offsets (floats) ----
#define EST_OFF  ((size_t)0)
#define OUT_OFF  ((size_t)131072)
#define QIJ_OFF  ((size_t)262144)
#define Z_OFF    ((size_t)1310720)
#define LH_OFF   ((size_t)68419584)

// ---- device scratch (no allocations allowed) ----
__device__ __align__(16) float g_t[Nn];
__device__ __align__(16) float g_efr[Nn*Dn];
__device__ __align__(16) float g_efi[Nn*Dn];
__device__ __align__(16) float g_Uqr[Bn*Nn*Dn];
__device__ __align__(16) float g_Uqi[Bn*Nn*Dn];
__device__ __align__(16) float g_Ukr[Bn*Nn*Dn];
__device__ __align__(16) float g_Uki[Bn*Nn*Dn];
__device__ __align__(16) float g_Uvr[Bn*Nn*Dn];
__device__ __align__(16) float g_Uvi[Bn*Nn*Dn];
__device__ __align__(16) float g_Vr [Bn*Nn*Dn];
__device__ __align__(16) float g_Vi [Bn*Nn*Dn];
__device__ __align__(16) float g_er [Bn*Nn*Dn];
__device__ __align__(16) float g_ei [Bn*Nn*Dn];
__device__ float g_nq[Bn*Nn];
__device__ float g_nk[Bn*Nn];

// ============================================================
// K0: t, e^{i phi} tables, lambda_h output
// ============================================================
__global__ void k_setup(const float* __restrict__ tm,
                        const float* __restrict__ lv,
                        float* __restrict__ out_lh)
{
    int idx = blockIdx.x * blockDim.x + threadIdx.x;   // 0..32767
    int i = idx >> 6;
    int d = idx & 63;
    float denom = tm[Nn - 1] - tm[0];
    float ti = tm[i] / denom;
    float lam = (d < 32) ? lv[d] : -lv[d - 32];
    float sph, cph;
    sincosf(ti * lam, &sph, &cph);
    g_efr[idx] = cph;
    g_efi[idx] = sph;
    if (d == 0) g_t[i] = ti;
    if (idx < 128) {
        float v;
        if (idx < 64) v = 0.f;
        else {
            int k = idx - 64;
            v = (k < 32) ? lv[k] : -lv[k - 32];
        }
        out_lh[idx] = v;
    }
}

// ============================================================
// K1: complex linear projections + twist by e^{-i phi} + norms
// grid (B*N, 3) ; block 64
// ============================================================
__global__ void k_proj(const float* __restrict__ Zq, const float* __restrict__ Zk,
                       const float* __restrict__ Zv,
                       const float* __restrict__ Wq, const float* __restrict__ bq,
                       const float* __restrict__ Wk, const float* __restrict__ bk,
                       const float* __restrict__ Wv, const float* __restrict__ bv)
{
    int row = blockIdx.x;          // b*N + i
    int m   = blockIdx.y;          // 0=q 1=k 2=v
    int d   = threadIdx.x;
    int b = row >> 9, i = row & 511;

    const float* Z  = (m == 0) ? Zq : (m == 1) ? Zk : Zv;
    const float* W  = (m == 0) ? Wq : (m == 1) ? Wk : Wv;
    const float* bb = (m == 0) ? bq : (m == 1) ? bk : bv;

    __shared__ float zr[64], zi[64];
    zr[d] = Z[((size_t)(b * 2 + 0) * Nn + i) * Dn + d];
    zi[d] = Z[((size_t)(b * 2 + 1) * Nn + i) * Dn + d];
    __syncthreads();

    const float* W0 = W;
    const float* W1 = W + Dn * Dn;
    float yr = bb[d], yi = bb[Dn + d];
#pragma unroll 8
    for (int e = 0; e < 64; e++) {
        float w0 = W0[d * 64 + e];
        float w1 = W1[d * 64 + e];
        float a = zr[e], c = zi[e];
        yr += a * w0 - c * w1;
        yi += a * w1 + c * w0;
    }

    float efr = g_efr[i * 64 + d];
    float efi = g_efi[i * 64 + d];
    // U = conj(ef) * y
    float ur = efr * yr + efi * yi;
    float ui = efr * yi - efi * yr;

    int o = row * 64 + d;
    if (m == 0)      { g_Uqr[o] = ur; g_Uqi[o] = ui; }
    else if (m == 1) { g_Ukr[o] = ur; g_Uki[o] = ui; }
    else             { g_Uvr[o] = ur; g_Uvi[o] = ui; g_Vr[o] = yr; g_Vi[o] = yi; }

    if (m < 2) {
        __shared__ float red[64];
        red[d] = ur * ur + ui * ui;
        __syncthreads();
        for (int s = 32; s > 0; s >>= 1) {
            if (d < s) red[d] += red[d + s];
            __syncthreads();
        }
        if (d == 0) {
            if (m == 0) g_nq[row] = red[0];
            else        g_nk[row] = red[0];
        }
    }
}

// ============================================================
// K2: scores + causal softmax + write A (and zero imag plane) + A@Uv
// grid (B*N) ; block 256
// ============================================================
__global__ void k_attn(const float* __restrict__ losq, const float* __restrict__ lgsq,
                       const float* __restrict__ nfp,  const float* __restrict__ taup,
                       float* __restrict__ out)
{
    int row = blockIdx.x;
    int b = row >> 9, i = row & 511;
    int tid = threadIdx.x;

    __shared__ __align__(16) float uq[128];   // [0:64) real, [64:128) imag
    __shared__ float s[512];
    __shared__ float red[256];

    if (tid < 128) {
        int d = tid & 63;
        uq[tid] = (tid < 64) ? g_Uqr[row * 64 + d] : g_Uqi[row * 64 + d];
    }
    __syncthreads();

    float lo   = losq[0] * losq[0];
    float lg   = lgsq[0] * lgsq[0] + EPSf;
    float nf2  = nfp[0] * nfp[0] + EPSf;
    float tau2 = taup[0] * taup[0];
    float ti   = g_t[i];
    float nqv  = g_nq[row];

    for (int j = tid; j < 512; j += 256) {
        float sc = -INFINITY;
        if (j <= i) {
            const float4* kr4 = (const float4*)(g_Ukr + (size_t)(b * 512 + j) * 64);
            const float4* ki4 = (const float4*)(g_Uki + (size_t)(b * 512 + j) * 64);
            const float4* qr4 = (const float4*)uq;
            const float4* qi4 = (const float4*)(uq + 64);
            float acc = 0.f;
#pragma unroll
            for (int e = 0; e < 16; e++) {
                float4 kr = kr4[e], ki = ki4[e];
                float4 qr = qr4[e], qi = qi4[e];
                acc += qr.x * kr.x + qr.y * kr.y + qr.z * kr.z + qr.w * kr.w
                     + qi.x * ki.x + qi.y * ki.y + qi.z * ki.z + qi.w * ki.w;
            }
            float R   = nqv + g_nk[b * 512 + j] - 2.f * acc;
            float vav = lo * fabsf(ti - g_t[j]) + lg;
            sc = -tau2 * logf(nf2 * vav + R);
        }
        s[j] = sc;
    }
    __syncthreads();

    // max reduce
    float mloc = fmaxf(s[tid], s[tid + 256]);
    red[tid] = mloc;
    __syncthreads();
    for (int st = 128; st > 0; st >>= 1) {
        if (tid < st) red[tid] = fmaxf(red[tid], red[tid + st]);
        __syncthreads();
    }
    float mx = red[0];
    __syncthreads();

    // exp + sum
    float e0 = expf(s[tid] - mx);
    float e1 = expf(s[tid + 256] - mx);
    s[tid] = e0;
    s[tid + 256] = e1;
    red[tid] = e0 + e1;
    __syncthreads();
    for (int st = 128; st > 0; st >>= 1) {
        if (tid < st) red[tid] += red[tid + st];
        __syncthreads();
    }
    float inv = 1.f / red[0];
    __syncthreads();

    // normalize, write A + zero imag plane
    float a0 = s[tid] * inv;
    float a1 = s[tid + 256] * inv;
    s[tid] = a0;
    s[tid + 256] = a1;
    size_t qoffr = QIJ_OFF + ((size_t)(b * 2 + 0) * 512 + i) * 512;
    size_t qoffi = QIJ_OFF + ((size_t)(b * 2 + 1) * 512 + i) * 512;
    out[qoffr + tid]       = a0;
    out[qoffr + tid + 256] = a1;
    out[qoffi + tid]       = 0.f;
    out[qoffi + tid + 256] = 0.f;
    __syncthreads();

    // er/ei = A @ Uv  (4 j-groups x 64 d)
    int grp = tid >> 6;
    int d   = tid & 63;
    float accr = 0.f, acci = 0.f;
    for (int j = grp; j <= i; j += 4) {
        float a = s[j];
        accr += a * g_Uvr[(size_t)(b * 512 + j) * 64 + d];
        acci += a * g_Uvi[(size_t)(b * 512 + j) * 64 + d];
    }
    red[tid] = accr;
    __syncthreads();
    float erv = 0.f;
    if (tid < 64) erv = red[tid] + red[tid + 64] + red[tid + 128] + red[tid + 192];
    __syncthreads();
    red[tid] = acci;
    __syncthreads();
    if (tid < 64) {
        float eiv = red[tid] + red[tid + 64] + red[tid + 128] + red[tid + 192];
        g_er[row * 64 + tid] = erv;
        g_ei[row * 64 + tid] = eiv;
    }
}

// ============================================================
// K3: estv / est_latent / P / output projection
// grid (B*N) ; block 64
// ============================================================
__global__ void k_epi(const float* __restrict__ Wp, const float* __restrict__ bp,
                      const float* __restrict__ etap, float* __restrict__ out)
{
    int row = blockIdx.x;
    int b = row >> 9, i = row & 511;
    int d = threadIdx.x;

    float efr = g_efr[i * 64 + d];
    float efi = g_efi[i * 64 + d];
    float er = g_er[row * 64 + d];
    float ei = g_ei[row * 64 + d];
    float estr = efr * er - efi * ei;
    float esti = efr * ei + efi * er;

    float eta = 1.f / (1.f + expf(-etap[d]));
    float g   = 1.f / (1.f + expf(-eta));
    float elr = (1.f - eta) * g_Vr[row * 64 + d] + g * estr;
    float eli = (1.f - eta) * g_Vi[row * 64 + d] + g * esti;

    out[EST_OFF + ((size_t)(b * 2 + 0) * 512 + i) * 64 + d] = elr;
    out[EST_OFF + ((size_t)(b * 2 + 1) * 512 + i) * 64 + d] = eli;

    __shared__ float pr[64], pi[64];
    pr[d] = efr * elr - efi * eli;
    pi[d] = efr * eli + efi * elr;
    __syncthreads();

    const float* W0 = Wp;
    const float* W1 = Wp + 4096;
    float yr = bp[d], yi = bp[64 + d];
#pragma unroll 8
    for (int e = 0; e < 64; e++) {
        float w0 = W0[d * 64 + e];
        float w1 = W1[d * 64 + e];
        float a = pr[e], c = pi[e];
        yr += a * w0 - c * w1;
        yi += a * w1 + c * w0;
    }
    out[OUT_OFF + ((size_t)(b * 2 + 0) * 512 + i) * 64 + d] = yr;
    out[OUT_OFF + ((size_t)(b * 2 + 1) * 512 + i) * 64 + d] = yi;
}

// ============================================================
// K4: Z_ij_hat_all — dominant 268 MB write. One block per (b,i),
// writes both real and imag planes, float4 vectorized.
// grid (B*N) ; block 256
// ============================================================
__global__ void k_zij(float* __restrict__ out)
{
    int row = blockIdx.x;
    int b = row >> 9, i = row & 511;
    int tid = threadIdx.x;

    __shared__ __align__(16) float efr[64], efi[64];
    if (tid < 64)            efr[tid]      = g_efr[i * 64 + tid];
    else if (tid < 128)      efi[tid - 64] = g_efi[i * 64 + (tid - 64)];
    __syncthreads();

    const float4* vr4 = (const float4*)(g_Uvr + (size_t)b * 512 * 64);
    const float4* vi4 = (const float4*)(g_Uvi + (size_t)b * 512 * 64);
    float4* zr4 = (float4*)(out + Z_OFF + ((size_t)(b * 2 + 0) * 512 + i) * 512 * 64);
    float4* zi4 = (float4*)(out + Z_OFF + ((size_t)(b * 2 + 1) * 512 + i) * 512 * 64);

    for (int k = tid; k < 512 * 16; k += 256) {
        int d = (k & 15) << 2;
        float4 vr = vr4[k];
        float4 vi = vi4[k];
        float e0 = efr[d],     f0 = efi[d];
        float e1 = efr[d + 1], f1 = efi[d + 1];
        float e2 = efr[d + 2], f2 = efi[d + 2];
        float e3 = efr[d + 3], f3 = efi[d + 3];
        float4 zr, zi;
        zr.x = e0 * vr.x - f0 * vi.x;  zi.x = e0 * vi.x + f0 * vr.x;
        zr.y = e1 * vr.y - f1 * vi.y;  zi.y = e1 * vi.y + f1 * vr.y;
        zr.z = e2 * vr.z - f2 * vi.z;  zi.z = e2 * vi.z + f2 * vr.z;
        zr.w = e3 * vr.w - f3 * vi.w;  zi.w = e3 * vi.w + f3 * vr.w;
        zr4[k] = zr;
        zi4[k] = zi;
    }
}

// ============================================================
extern "C" void kernel_launch(void* const* d_in, const int* in_sizes, int n_in,
                              void* d_out, int out_size)
{
    const float* Zq   = (const float*)d_in[0];
    const float* Zk   = (const float*)d_in[1];
    const float* Zv   = (const float*)d_in[2];
    const float* tm   = (const float*)d_in[3];
    const float* Wq   = (const float*)d_in[4];
    const float* bq   = (const float*)d_in[5];
    const float* Wk   = (const float*)d_in[6];
    const float* bk   = (const float*)d_in[7];
    const float* Wv   = (const float*)d_in[8];
    const float* bv   = (const float*)d_in[9];
    const float* Wp   = (const float*)d_in[10];
    const float* bp   = (const float*)d_in[11];
    const float* lv   = (const float*)d_in[12];
    const float* losq = (const float*)d_in[13];
    const float* lgsq = (const float*)d_in[14];
    const float* nf   = (const float*)d_in[15];
    const float* tau  = (const float*)d_in[16];
    const float* etap = (const float*)d_in[17];
    float* out = (float*)d_out;

    k_setup<<<64, 512>>>(tm, lv, out + LH_OFF);
    k_proj<<<dim3(Bn * Nn, 3), 64>>>(Zq, Zk, Zv, Wq, bq, Wk, bk, Wv, bv);
    k_attn<<<Bn * Nn, 256>>>(losq, lgsq, nf, tau, out);
    k_epi<<<Bn * Nn, 64>>>(Wp, bp, etap, out);
    k_zij<<<Bn * Nn, 256>>>(out);
}

// round 2
// speedup vs baseline: 2.2362x; 2.2362x over previous
#include <cuda_runtime.h>
#include <math.h>

#define Bn 2
#define Nn 512
#define Dn 64
#define EPSf 1e-8f

// ---- output section offsets (floats) ----
#define EST_OFF  ((size_t)0)
#define OUT_OFF  ((size_t)131072)
#define QIJ_OFF  ((size_t)262144)
#define Z_OFF    ((size_t)1310720)
#define LH_OFF   ((size_t)68419584)

// ---- device scratch ----
__device__ __align__(16) float g_t[Nn];
__device__ __align__(16) float g_efr[Nn*Dn];
__device__ __align__(16) float g_efi[Nn*Dn];
__device__ __align__(16) float g_Uqr[Bn*Nn*Dn];
__device__ __align__(16) float g_Uqi[Bn*Nn*Dn];
__device__ __align__(16) float g_UkrT[Bn*Dn*Nn];   // [b][d][j]
__device__ __align__(16) float g_UkiT[Bn*Dn*Nn];
__device__ __align__(16) float g_Uvr[Bn*Nn*Dn];
__device__ __align__(16) float g_Uvi[Bn*Nn*Dn];
__device__ __align__(16) float g_Vr [Bn*Nn*Dn];
__device__ __align__(16) float g_Vi [Bn*Nn*Dn];
__device__ __align__(16) float g_er [Bn*Nn*Dn];
__device__ __align__(16) float g_ei [Bn*Nn*Dn];
__device__ float g_nq[Bn*Nn];
__device__ float g_nk[Bn*Nn];

// ============================================================
// K0: t, e^{i phi} tables, lambda_h output
// ============================================================
__global__ void k_setup(const float* __restrict__ tm,
                        const float* __restrict__ lv,
                        float* __restrict__ out_lh)
{
    int idx = blockIdx.x * blockDim.x + threadIdx.x;   // 0..32767
    int i = idx >> 6;
    int d = idx & 63;
    float denom = tm[Nn - 1] - tm[0];
    float ti = tm[i] / denom;
    float lam = (d < 32) ? lv[d] : -lv[d - 32];
    float sph, cph;
    sincosf(ti * lam, &sph, &cph);
    g_efr[idx] = cph;
    g_efi[idx] = sph;
    if (d == 0) g_t[i] = ti;
    if (idx < 128) {
        float v;
        if (idx < 64) v = 0.f;
        else {
            int k = idx - 64;
            v = (k < 32) ? lv[k] : -lv[k - 32];
        }
        out_lh[idx] = v;
    }
}

// ============================================================
// K1: complex projections + twist. Weights staged in padded smem.
// grid (64, 3) ; block 256 ; 16 rows per block (4 concurrent x 4 iters)
// ============================================================
__global__ void __launch_bounds__(256) k_proj(
    const float* __restrict__ Zq, const float* __restrict__ Zk,
    const float* __restrict__ Zv,
    const float* __restrict__ Wq, const float* __restrict__ bq,
    const float* __restrict__ Wk, const float* __restrict__ bk,
    const float* __restrict__ Wv, const float* __restrict__ bv)
{
    int m   = blockIdx.y;          // 0=q 1=k 2=v
    int tid = threadIdx.x;
    int d   = tid & 63;
    int sub = tid >> 6;

    const float* Z  = (m == 0) ? Zq : (m == 1) ? Zk : Zv;
    const float* W  = (m == 0) ? Wq : (m == 1) ? Wk : Wv;
    const float* bb = (m == 0) ? bq : (m == 1) ? bk : bv;

    __shared__ float sW0[64 * 65];
    __shared__ float sW1[64 * 65];
    __shared__ float zbuf[4][2][64];
    __shared__ float part[8];

    for (int idx = tid; idx < 4096; idx += 256) {
        int r = idx >> 6, c = idx & 63;
        sW0[r * 65 + c] = W[idx];
        sW1[r * 65 + c] = W[4096 + idx];
    }
    float bR = bb[d], bI = bb[64 + d];
    __syncthreads();

    for (int it = 0; it < 4; it++) {
        int row = blockIdx.x * 16 + it * 4 + sub;    // 0..1023
        int b = row >> 9, i = row & 511;

        zbuf[sub][0][d] = Z[((size_t)(b * 2 + 0) * Nn + i) * Dn + d];
        zbuf[sub][1][d] = Z[((size_t)(b * 2 + 1) * Nn + i) * Dn + d];
        __syncthreads();

        float yr = bR, yi = bI;
#pragma unroll 16
        for (int e = 0; e < 64; e++) {
            float w0 = sW0[d * 65 + e];
            float w1 = sW1[d * 65 + e];
            float a = zbuf[sub][0][e];
            float c = zbuf[sub][1][e];
            yr += a * w0 - c * w1;
            yi += a * w1 + c * w0;
        }

        float efr = g_efr[i * 64 + d];
        float efi = g_efi[i * 64 + d];
        float ur = efr * yr + efi * yi;     // U = conj(ef) * y
        float ui = efr * yi - efi * yr;

        int o = row * 64 + d;
        if (m == 0)      { g_Uqr[o] = ur; g_Uqi[o] = ui; }
        else if (m == 1) { g_UkrT[b * 32768 + d * 512 + i] = ur;
                           g_UkiT[b * 32768 + d * 512 + i] = ui; }
        else             { g_Uvr[o] = ur; g_Uvi[o] = ui;
                           g_Vr[o] = yr;  g_Vi[o] = yi; }

        if (m < 2) {
            float v = ur * ur + ui * ui;
#pragma unroll
            for (int off = 16; off > 0; off >>= 1)
                v += __shfl_down_sync(0xffffffffu, v, off);
            if ((tid & 31) == 0) part[tid >> 5] = v;
        }
        __syncthreads();
        if (m < 2 && d == 0) {
            float tot = part[sub * 2] + part[sub * 2 + 1];
            if (m == 0) g_nq[row] = tot;
            else        g_nk[row] = tot;
        }
    }
}

// ============================================================
// K2: scores (coalesced transposed K) + softmax + A write + A@Uv
// grid (B*N) ; block 256
// ============================================================
__global__ void __launch_bounds__(256) k_attn(
    const float* __restrict__ losq, const float* __restrict__ lgsq,
    const float* __restrict__ nfp,  const float* __restrict__ taup,
    float* __restrict__ out)
{
    int row = blockIdx.x;
    int b = row >> 9, i = row & 511;
    int tid = threadIdx.x;

    __shared__ __align__(16) float uq[128];   // [0:64) real, [64:128) imag
    __shared__ float s[512];
    __shared__ float red[256];

    if (tid < 128) {
        int d = tid & 63;
        uq[tid] = (tid < 64) ? g_Uqr[row * 64 + d] : g_Uqi[row * 64 + d];
    }
    __syncthreads();

    float lo   = losq[0] * losq[0];
    float lg   = lgsq[0] * lgsq[0] + EPSf;
    float nf2  = nfp[0] * nfp[0] + EPSf;
    float tau2 = taup[0] * taup[0];
    float ti   = g_t[i];
    float nqv  = g_nq[row];

    const float* krT = g_UkrT + b * 32768;
    const float* kiT = g_UkiT + b * 32768;

#pragma unroll
    for (int jj = 0; jj < 2; jj++) {
        int j = tid + jj * 256;
        float sc = -INFINITY;
        if (j <= i) {
            float acc = 0.f;
            const float* kr = krT + j;
            const float* ki = kiT + j;
#pragma unroll 16
            for (int e = 0; e < 64; e++)
                acc += uq[e] * kr[e * 512] + uq[64 + e] * ki[e * 512];
            float R   = nqv + g_nk[b * 512 + j] - 2.f * acc;
            float vav = lo * fabsf(ti - g_t[j]) + lg;
            sc = -tau2 * logf(nf2 * vav + R);
        }
        s[j] = sc;
    }
    __syncthreads();

    // max reduce
    red[tid] = fmaxf(s[tid], s[tid + 256]);
    __syncthreads();
    for (int st = 128; st > 0; st >>= 1) {
        if (tid < st) red[tid] = fmaxf(red[tid], red[tid + st]);
        __syncthreads();
    }
    float mx = red[0];
    __syncthreads();

    // exp + sum
    float e0 = expf(s[tid] - mx);
    float e1 = expf(s[tid + 256] - mx);
    s[tid] = e0;
    s[tid + 256] = e1;
    red[tid] = e0 + e1;
    __syncthreads();
    for (int st = 128; st > 0; st >>= 1) {
        if (tid < st) red[tid] += red[tid + st];
        __syncthreads();
    }
    float inv = 1.f / red[0];
    __syncthreads();

    float a0 = s[tid] * inv;
    float a1 = s[tid + 256] * inv;
    s[tid] = a0;
    s[tid + 256] = a1;
    size_t qoffr = QIJ_OFF + ((size_t)(b * 2 + 0) * 512 + i) * 512;
    size_t qoffi = QIJ_OFF + ((size_t)(b * 2 + 1) * 512 + i) * 512;
    out[qoffr + tid]       = a0;
    out[qoffr + tid + 256] = a1;
    out[qoffi + tid]       = 0.f;
    out[qoffi + tid + 256] = 0.f;
    __syncthreads();

    // er/ei = A @ Uv  (coalesced over d)
    int grp = tid >> 6;
    int d   = tid & 63;
    float accr = 0.f, acci = 0.f;
    for (int j = grp; j <= i; j += 4) {
        float a = s[j];
        accr += a * g_Uvr[(size_t)(b * 512 + j) * 64 + d];
        acci += a * g_Uvi[(size_t)(b * 512 + j) * 64 + d];
    }
    red[tid] = accr;
    __syncthreads();
    float erv = 0.f;
    if (tid < 64) erv = red[tid] + red[tid + 64] + red[tid + 128] + red[tid + 192];
    __syncthreads();
    red[tid] = acci;
    __syncthreads();
    if (tid < 64) {
        float eiv = red[tid] + red[tid + 64] + red[tid + 128] + red[tid + 192];
        g_er[row * 64 + tid] = erv;
        g_ei[row * 64 + tid] = eiv;
    }
}

// ============================================================
// K3: estv / est_latent / P / output projection. Wp staged in smem.
// grid 64 ; block 256 ; 16 rows per block
// ============================================================
__global__ void __launch_bounds__(256) k_epi(
    const float* __restrict__ Wp, const float* __restrict__ bp,
    const float* __restrict__ etap, float* __restrict__ out)
{
    int tid = threadIdx.x;
    int d   = tid & 63;
    int sub = tid >> 6;

    __shared__ float sW0[64 * 65];
    __shared__ float sW1[64 * 65];
    __shared__ float pbuf[4][2][64];

    for (int idx = tid; idx < 4096; idx += 256) {
        int r = idx >> 6, c = idx & 63;
        sW0[r * 65 + c] = Wp[idx];
        sW1[r * 65 + c] = Wp[4096 + idx];
    }
    float bR = bp[d], bI = bp[64 + d];
    float eta = 1.f / (1.f + expf(-etap[d]));
    float g   = 1.f / (1.f + expf(-eta));
    __syncthreads();

    for (int it = 0; it < 4; it++) {
        int row = blockIdx.x * 16 + it * 4 + sub;
        int b = row >> 9, i = row & 511;

        float efr = g_efr[i * 64 + d];
        float efi = g_efi[i * 64 + d];
        float er = g_er[row * 64 + d];
        float ei = g_ei[row * 64 + d];
        float estr = efr * er - efi * ei;
        float esti = efr * ei + efi * er;

        float elr = (1.f - eta) * g_Vr[row * 64 + d] + g * estr;
        float eli = (1.f - eta) * g_Vi[row * 64 + d] + g * esti;

        out[EST_OFF + ((size_t)(b * 2 + 0) * 512 + i) * 64 + d] = elr;
        out[EST_OFF + ((size_t)(b * 2 + 1) * 512 + i) * 64 + d] = eli;

        pbuf[sub][0][d] = efr * elr - efi * eli;
        pbuf[sub][1][d] = efr * eli + efi * elr;
        __syncthreads();

        float yr = bR, yi = bI;
#pragma unroll 16
        for (int e = 0; e < 64; e++) {
            float w0 = sW0[d * 65 + e];
            float w1 = sW1[d * 65 + e];
            float a = pbuf[sub][0][e];
            float c = pbuf[sub][1][e];
            yr += a * w0 - c * w1;
            yi += a * w1 + c * w0;
        }
        out[OUT_OFF + ((size_t)(b * 2 + 0) * 512 + i) * 64 + d] = yr;
        out[OUT_OFF + ((size_t)(b * 2 + 1) * 512 + i) * 64 + d] = yi;
        __syncthreads();
    }
}

// ============================================================
// K4: Z_ij_hat_all — 268 MB write, streaming stores.
// grid (B*N) ; block 256
// ============================================================
__global__ void __launch_bounds__(256) k_zij(float* __restrict__ out)
{
    int row = blockIdx.x;
    int b = row >> 9, i = row & 511;
    int tid = threadIdx.x;

    __shared__ __align__(16) float efr[64], efi[64];
    if (tid < 64)            efr[tid]      = g_efr[i * 64 + tid];
    else if (tid < 128)      efi[tid - 64] = g_efi[i * 64 + (tid - 64)];
    __syncthreads();

    const float4* vr4 = (const float4*)(g_Uvr + (size_t)b * 512 * 64);
    const float4* vi4 = (const float4*)(g_Uvi + (size_t)b * 512 * 64);
    float4* zr4 = (float4*)(out + Z_OFF + ((size_t)(b * 2 + 0) * 512 + i) * 512 * 64);
    float4* zi4 = (float4*)(out + Z_OFF + ((size_t)(b * 2 + 1) * 512 + i) * 512 * 64);

    for (int k = tid; k < 512 * 16; k += 256) {
        int d = (k & 15) << 2;
        float4 vr = vr4[k];
        float4 vi = vi4[k];
        float e0 = efr[d],     f0 = efi[d];
        float e1 = efr[d + 1], f1 = efi[d + 1];
        float e2 = efr[d + 2], f2 = efi[d + 2];
        float e3 = efr[d + 3], f3 = efi[d + 3];
        float4 zr, zi;
        zr.x = e0 * vr.x - f0 * vi.x;  zi.x = e0 * vi.x + f0 * vr.x;
        zr.y = e1 * vr.y - f1 * vi.y;  zi.y = e1 * vi.y + f1 * vr.y;
        zr.z = e2 * vr.z - f2 * vi.z;  zi.z = e2 * vi.z + f2 * vr.z;
        zr.w = e3 * vr.w - f3 * vi.w;  zi.w = e3 * vi.w + f3 * vr.w;
        __stcs(&zr4[k], zr);
        __stcs(&zi4[k], zi);
    }
}

// ============================================================
extern "C" void kernel_launch(void* const* d_in, const int* in_sizes, int n_in,
                              void* d_out, int out_size)
{
    const float* Zq   = (const float*)d_in[0];
    const float* Zk   = (const float*)d_in[1];
    const float* Zv   = (const float*)d_in[2];
    const float* tm   = (const float*)d_in[3];
    const float* Wq   = (const float*)d_in[4];
    const float* bq   = (const float*)d_in[5];
    const float* Wk   = (const float*)d_in[6];
    const float* bk   = (const float*)d_in[7];
    const float* Wv   = (const float*)d_in[8];
    const float* bv   = (const float*)d_in[9];
    const float* Wp   = (const float*)d_in[10];
    const float* bp   = (const float*)d_in[11];
    const float* lv   = (const float*)d_in[12];
    const float* losq = (const float*)d_in[13];
    const float* lgsq = (const float*)d_in[14];
    const float* nf   = (const float*)d_in[15];
    const float* tau  = (const float*)d_in[16];
    const float* etap = (const float*)d_in[17];
    float* out = (float*)d_out;

    // Lazy-created side stream + events (created on the un-captured
    // correctness call; only record/wait are captured into the graph).
    static cudaStream_t s_z = nullptr;
    static cudaEvent_t ev_fork = nullptr, ev_join = nullptr;
    if (s_z == nullptr) {
        cudaStreamCreateWithFlags(&s_z, cudaStreamNonBlocking);
        cudaEventCreateWithFlags(&ev_fork, cudaEventDisableTiming);
        cudaEventCreateWithFlags(&ev_join, cudaEventDisableTiming);
    }

    k_setup<<<64, 512>>>(tm, lv, out + LH_OFF);
    k_proj<<<dim3(64, 3), 256>>>(Zq, Zk, Zv, Wq, bq, Wk, bk, Wv, bv);

    // fork: Z-plane writer runs concurrently with attention + epilogue
    cudaEventRecord(ev_fork, 0);
    cudaStreamWaitEvent(s_z, ev_fork, 0);
    k_zij<<<Bn * Nn, 256, 0, s_z>>>(out);
    cudaEventRecord(ev_join, s_z);

    k_attn<<<Bn * Nn, 256>>>(losq, lgsq, nf, tau, out);
    k_epi<<<64, 256>>>(Wp, bp, etap, out);

    // join
    cudaStreamWaitEvent(0, ev_join, 0);
}